// round 15
// baseline (speedup 1.0000x reference)
#include <cuda_runtime.h>

// ---------------- problem constants ----------------
#define BB   32      // batch
#define SS   256     // seq len
#define II   128     // input dim
#define HH   512     // hidden
#define CC   64      // out channels
#define DD   17      // buffer depth (MAX_DELAY+1)
#define TENC 256
#define TDEC 64

// ---------------- kernel config ----------------
#define NBLK 128     // blocks (<=148 SMs -> all resident, barrier-safe)
#define NTHR 256     // threads per block
#define NC   4       // hidden columns per block (NBLK*NC == HH)
#define IROW 644     // padded input row stride (floats) -> conflict-free
#define WSI  648     // padded W_in/W_comb column stride
#define WSH  520     // padded 512-row weight column stride

// packed fp32x2 FMA (sm_100+; only reachable via PTX) -- 2 MACs / instruction
#define FMA2(acc, a, b) \
    asm("fma.rn.f32x2 %0, %1, %2, %0;" : "+l"(acc) : "l"(a), "l"(b))
#define UNPK(lo, hi, v) \
    asm("mov.b64 {%0, %1}, %2;" : "=f"(lo), "=f"(hi) : "l"(v))

struct Smem {
    // float4/ulonglong2-accessed arrays first (16B-aligned offsets)
    float inp[BB * IROW];          // staged activations (32 x up-to-640)
    float w_in[NC * WSI];          // W_in[:, jb..jb+3] transposed (col-major)
    float w_cm[NC * WSI];          // W_comb[:, jb..jb+3] transposed (col-major)
    float w_tu[NC * WSH];
    float w_me[NC * WSH];
    float w_ot[HH];                // W_out[:, blk] (blocks 0..63 only)
    // scalar-accessed
    float buf[BB * NC * DD];       // circular delay buffer, stride 17 (odd -> conflict-free)
    float hs [BB * NC];
    float psA[NTHR];
    float psB[NTHR];
    float psO[64];
    float sb_in[NC], sb_cm[NC], sb_tu[NC], sb_me[NC];
    float sb_ot;
    int   len[BB];
};

__device__ float g_h0[BB * HH];
__device__ float g_hx[BB * HH];
__device__ float g_wcomb[(HH + II) * HH];   // W_in @ W_pass, (640,512) row-major
__device__ float g_bcomb[HH];               // b_in @ W_pass + b_pass
__device__ unsigned g_arr;
__device__ unsigned g_gen;

// ---------------- pre-kernel: W_comb = W_in @ W_pass (tiled), b_comb folded ----
// grid (20, 8): block computes rows r0..r0+31 x cols c0..c0+63.
// blocks with blockIdx.x==0 also accumulate b_comb for their 64 columns.
__global__ void __launch_bounds__(256, 1)
build_wcomb(const float* __restrict__ Win, const float* __restrict__ Wps,
            const float* __restrict__ bin, const float* __restrict__ bps) {
    __shared__ float As[32][33];     // A^T tile: As[k][m]
    __shared__ float Bs[32][64];     // B tile:   Bs[k][n]
    __shared__ float bi[32];
    const int tid = threadIdx.x;
    const int r0 = blockIdx.x * 32;
    const int c0 = blockIdx.y * 64;
    const int tx = tid & 15;         // col group (4 cols)
    const int ty = tid >> 4;         // row group (2 rows)
    const bool do_b = (blockIdx.x == 0);

    float acc[2][4] = {};
    float accD[4] = {};

    for (int k0 = 0; k0 < HH; k0 += 32) {
        // load A tile (32 rows x 32 k), store transposed
        {
            int row = tid >> 3, kq = tid & 7;
            float4 va = *reinterpret_cast<const float4*>(
                Win + (size_t)(r0 + row) * HH + k0 + kq * 4);
            As[kq * 4 + 0][row] = va.x; As[kq * 4 + 1][row] = va.y;
            As[kq * 4 + 2][row] = va.z; As[kq * 4 + 3][row] = va.w;
        }
        // load B tile (32 k-rows x 64 cols)
        #pragma unroll
        for (int i = tid; i < 512; i += 256) {
            int row = i >> 4, cq = i & 15;
            float4 vb = *reinterpret_cast<const float4*>(
                Wps + (size_t)(k0 + row) * HH + c0 + cq * 4);
            *reinterpret_cast<float4*>(&Bs[row][cq * 4]) = vb;
        }
        if (do_b && tid < 32) bi[tid] = bin[k0 + tid];
        __syncthreads();
        #pragma unroll 8
        for (int k = 0; k < 32; ++k) {
            float a0 = As[k][ty * 2 + 0];
            float a1 = As[k][ty * 2 + 1];
            float4 bv = *reinterpret_cast<const float4*>(&Bs[k][tx * 4]);
            acc[0][0] = fmaf(a0, bv.x, acc[0][0]); acc[0][1] = fmaf(a0, bv.y, acc[0][1]);
            acc[0][2] = fmaf(a0, bv.z, acc[0][2]); acc[0][3] = fmaf(a0, bv.w, acc[0][3]);
            acc[1][0] = fmaf(a1, bv.x, acc[1][0]); acc[1][1] = fmaf(a1, bv.y, acc[1][1]);
            acc[1][2] = fmaf(a1, bv.z, acc[1][2]); acc[1][3] = fmaf(a1, bv.w, acc[1][3]);
            if (do_b && ty == 0) {
                float bk = bi[k];
                accD[0] = fmaf(bk, bv.x, accD[0]); accD[1] = fmaf(bk, bv.y, accD[1]);
                accD[2] = fmaf(bk, bv.z, accD[2]); accD[3] = fmaf(bk, bv.w, accD[3]);
            }
        }
        __syncthreads();
    }
    #pragma unroll
    for (int rr = 0; rr < 2; ++rr) {
        float4 v = make_float4(acc[rr][0], acc[rr][1], acc[rr][2], acc[rr][3]);
        *reinterpret_cast<float4*>(
            &g_wcomb[(size_t)(r0 + ty * 2 + rr) * HH + c0 + tx * 4]) = v;
    }
    if (do_b && ty == 0) {
        int c = c0 + tx * 4;
        g_bcomb[c + 0] = accD[0] + bps[c + 0];
        g_bcomb[c + 1] = accD[1] + bps[c + 1];
        g_bcomb[c + 2] = accD[2] + bps[c + 2];
        g_bcomb[c + 3] = accD[3] + bps[c + 3];
    }
}

// sense-reversing grid barrier (all NBLK blocks resident by construction)
__device__ __forceinline__ void grid_sync() {
    __syncthreads();
    if (threadIdx.x == 0) {
        volatile unsigned* vg = &g_gen;
        unsigned gen = *vg;
        __threadfence();                       // release my block's stores (cumulative)
        if (atomicAdd(&g_arr, 1u) == NBLK - 1u) {
            g_arr = 0u;
            __threadfence();
            atomicAdd(&g_gen, 1u);
        } else {
            while (*vg == gen) { __nanosleep(32); }
            __threadfence();                   // acquire
        }
    }
    __syncthreads();
}

// one recurrence step, two phases:
//   phase 1: h1 = [h0,x]@W_in, p = [h0,x]@W_comb (one k-loop), select -> h
//   phase 2: tau/mem gemms + circular buffer update
template<bool DEC>
__device__ __forceinline__ void rnn_step(
    Smem* s, const float* __restrict__ x, float* __restrict__ out,
    int g, int t, int jb, int blk, int tid, int c, int b, int half)
{
    // ================= phase 1 =================
    for (int i = tid; i < BB * (HH / 4); i += NTHR) {
        int rb = i >> 7, k4 = i & 127;
        float4 v = __ldcg(reinterpret_cast<const float4*>(g_h0 + rb * HH + (k4 << 2)));
        *reinterpret_cast<float4*>(s->inp + rb * IROW + (k4 << 2)) = v;
    }
    if (!DEC) {
        for (int i = tid; i < BB * (II / 4); i += NTHR) {
            int rb = i >> 5, k4 = i & 31;
            float4 v = *reinterpret_cast<const float4*>(
                x + (size_t)rb * (SS * II) + (size_t)t * II + (k4 << 2));
            *reinterpret_cast<float4*>(s->inp + rb * IROW + HH + (k4 << 2)) = v;
        }
    }
    __syncthreads();
    if (!DEC) {
        // encode: h1 and p in ONE k-loop over K=640 (packed f32x2 FMAs)
        const int K2 = (HH + II) >> 1;
        const ulonglong2* wi = reinterpret_cast<const ulonglong2*>(s->w_in + c * WSI + half * K2);
        const ulonglong2* wc = reinterpret_cast<const ulonglong2*>(s->w_cm + c * WSI + half * K2);
        const ulonglong2* ip = reinterpret_cast<const ulonglong2*>(s->inp + b * IROW + half * K2);
        unsigned long long aA0 = 0ULL, aA1 = 0ULL, aP0 = 0ULL, aP1 = 0ULL;
        #pragma unroll 8
        for (int i = 0; i < K2 / 4; ++i) {
            ulonglong2 V = ip[i];
            ulonglong2 W = wi[i];
            FMA2(aA0, W.x, V.x); FMA2(aA1, W.y, V.y);
            ulonglong2 U = wc[i];
            FMA2(aP0, U.x, V.x); FMA2(aP1, U.y, V.y);
        }
        float a0, a1, a2, a3, p0, p1, p2, p3;
        UNPK(a0, a1, aA0); UNPK(a2, a3, aA1);
        UNPK(p0, p1, aP0); UNPK(p2, p3, aP1);
        s->psA[tid] = (a0 + a1) + (a2 + a3);
        s->psB[tid] = (p0 + p1) + (p2 + p3);
    } else {
        // decode: p = h0@W_comb[:512]  (+ fold out = h0@W_out for blocks < CC)
        const int K2 = HH >> 1;
        const ulonglong2* wc = reinterpret_cast<const ulonglong2*>(s->w_cm + c * WSI + half * K2);
        const ulonglong2* ip = reinterpret_cast<const ulonglong2*>(s->inp + b * IROW + half * K2);
        unsigned long long aP0 = 0ULL, aP1 = 0ULL;
        if (blk < CC) {
            const ulonglong2* op = reinterpret_cast<const ulonglong2*>(s->w_ot + half * K2);
            unsigned long long aO0 = 0ULL, aO1 = 0ULL;
            #pragma unroll 8
            for (int i = 0; i < K2 / 4; ++i) {
                ulonglong2 V = ip[i];
                ulonglong2 U = wc[i];
                FMA2(aP0, U.x, V.x); FMA2(aP1, U.y, V.y);
                ulonglong2 O = op[i];
                FMA2(aO0, O.x, V.x); FMA2(aO1, O.y, V.y);
            }
            float o0, o1, o2, o3, p0, p1, p2, p3;
            UNPK(o0, o1, aO0); UNPK(o2, o3, aO1);
            UNPK(p0, p1, aP0); UNPK(p2, p3, aP1);
            if (c == 0) s->psO[(half << 5) | b] = (o0 + o1) + (o2 + o3);
            s->psB[tid] = (p0 + p1) + (p2 + p3);
        } else {
            #pragma unroll 8
            for (int i = 0; i < K2 / 4; ++i) {
                ulonglong2 V = ip[i];
                ulonglong2 U = wc[i];
                FMA2(aP0, U.x, V.x); FMA2(aP1, U.y, V.y);
            }
            float p0, p1, p2, p3;
            UNPK(p0, p1, aP0); UNPK(p2, p3, aP1);
            s->psB[tid] = (p0 + p1) + (p2 + p3);
        }
    }
    __syncthreads();
    if (tid < 128) {
        float p = s->psB[tid] + s->psB[tid + 128] + s->sb_cm[c];
        float hv;
        if (DEC) hv = p;
        else {
            float h1 = s->psA[tid] + s->psA[tid + 128] + s->sb_in[c];
            hv = (t < s->len[b]) ? p : h1;     // m in {0,1} -> exact select
        }
        s->hs[(b << 2) | c] = hv;
        __stcg(&g_hx[b * HH + jb + c], hv);
    }
    if (DEC && blk < CC && tid < BB) {
        float ov = s->psO[tid] + s->psO[tid + 32] + s->sb_ot;
        out[tid * (TDEC * CC) + t * CC + blk] = ov;
    }
    grid_sync();

    // ============ phase 2: tau/mem gemms + circular buffer update ============
    for (int i = tid; i < BB * (HH / 4); i += NTHR) {
        int rb = i >> 7, k4 = i & 127;
        float4 v = __ldcg(reinterpret_cast<const float4*>(g_hx + rb * HH + (k4 << 2)));
        *reinterpret_cast<float4*>(s->inp + rb * IROW + (k4 << 2)) = v;
    }
    __syncthreads();
    {
        const int K2 = HH >> 1;
        const ulonglong2* wt = reinterpret_cast<const ulonglong2*>(s->w_tu + c * WSH + half * K2);
        const ulonglong2* wm = reinterpret_cast<const ulonglong2*>(s->w_me + c * WSH + half * K2);
        const ulonglong2* ip = reinterpret_cast<const ulonglong2*>(s->inp + b * IROW + half * K2);
        unsigned long long aA0 = 0ULL, aA1 = 0ULL, aM0 = 0ULL, aM1 = 0ULL;
        #pragma unroll 8
        for (int i = 0; i < K2 / 4; ++i) {
            ulonglong2 V = ip[i];
            ulonglong2 W = wt[i];
            FMA2(aA0, W.x, V.x); FMA2(aA1, W.y, V.y);
            ulonglong2 U = wm[i];
            FMA2(aM0, U.x, V.x); FMA2(aM1, U.y, V.y);
        }
        float a0, a1, a2, a3, m0, m1, m2, m3;
        UNPK(a0, a1, aA0); UNPK(a2, a3, aA1);
        UNPK(m0, m1, aM0); UNPK(m2, m3, aM1);
        s->psA[tid] = (a0 + a1) + (a2 + a3);
        s->psB[tid] = (m0 + m1) + (m2 + m3);
    }
    __syncthreads();
    if (tid < 128) {
        float tl = s->psA[tid] + s->psA[tid + 128] + s->sb_tu[c];
        float ml = s->psB[tid] + s->psB[tid + 128] + s->sb_me[c];
        float tau = 16.f / (1.f + expf(-tl));
        tau = fminf(fmaxf(tau, 1.f), 16.f);
        float mem = 1.f / (1.f + expf(-ml));
        float hv  = s->hs[(b << 2) | c];
        float* bf = s->buf + ((b << 2) | c) * DD;
        // logical k at step g lives at phys (g+k)%17; newbuf[16]=0 -> zero slot g%17,
        // add w_d*h into phys (g+d)%17 for d=1..16, next h0 = phys (g+1)%17
        int s0 = g % DD;
        bf[s0] = 0.f;
        int sl = s0;
        #pragma unroll
        for (int d = 1; d <= 16; ++d) {
            ++sl; if (sl == DD) sl = 0;
            float w = mem / (1.f + fabsf(tau - (float)d));
            bf[sl] = fmaf(w, hv, bf[sl]);
        }
        int s1 = s0 + 1; if (s1 == DD) s1 = 0;
        __stcg(&g_h0[b * HH + jb + c], bf[s1]);
    }
    grid_sync();
}

__global__ void __launch_bounds__(NTHR, 1)
delay_rnn_kernel(const float* __restrict__ x,
                 const int*   __restrict__ lengths,
                 const float* __restrict__ Win,  const float* __restrict__ b_in,
                 const float* __restrict__ Wtu,  const float* __restrict__ b_tu,
                 const float* __restrict__ Wme,  const float* __restrict__ b_me,
                 const float* __restrict__ Wot,  const float* __restrict__ b_ot,
                 float* __restrict__ out)
{
    extern __shared__ __align__(16) char smem_raw[];
    Smem* s = reinterpret_cast<Smem*>(smem_raw);
    const int tid  = threadIdx.x;
    const int blk  = blockIdx.x;
    const int jb   = blk * NC;
    const int c    = tid & 3;
    const int b    = (tid >> 2) & 31;
    const int half = tid >> 7;

    // -------- one-time setup: weights -> smem (transposed, padded) --------
    for (int i = tid; i < (HH + II) * NC; i += NTHR) {
        int cc = i & 3, k = i >> 2;
        s->w_in[cc * WSI + k] = Win[(size_t)k * HH + jb + cc];
        s->w_cm[cc * WSI + k] = g_wcomb[(size_t)k * HH + jb + cc];
    }
    for (int i = tid; i < HH * NC; i += NTHR) {
        int cc = i & 3, k = i >> 2;
        s->w_tu[cc * WSH + k] = Wtu[(size_t)k * HH + jb + cc];
        s->w_me[cc * WSH + k] = Wme[(size_t)k * HH + jb + cc];
    }
    if (blk < CC)
        for (int k = tid; k < HH; k += NTHR) s->w_ot[k] = Wot[(size_t)k * CC + blk];
    if (tid < NC) {
        s->sb_in[tid] = b_in[jb + tid];
        s->sb_cm[tid] = g_bcomb[jb + tid];
        s->sb_tu[tid] = b_tu[jb + tid];
        s->sb_me[tid] = b_me[jb + tid];
    }
    if (tid == 0) s->sb_ot = (blk < CC) ? b_ot[blk] : 0.f;
    if (tid < BB) s->len[tid] = lengths[tid];
    for (int i = tid; i < BB * NC * DD; i += NTHR) s->buf[i] = 0.f;
    if (tid < 128) __stcg(&g_h0[b * HH + jb + c], 0.f);   // buffer[:,:,0] starts zero
    grid_sync();

    // -------- encode: 256 steps --------
    for (int g = 0; g < TENC; ++g)
        rnn_step<false>(s, x, out, g, g, jb, blk, tid, c, b, half);
    // -------- decode: 64 steps --------
    for (int g = TENC; g < TENC + TDEC; ++g)
        rnn_step<true>(s, x, out, g, g - TENC, jb, blk, tid, c, b, half);
}

extern "C" void kernel_launch(void* const* d_in, const int* in_sizes, int n_in,
                              void* d_out, int out_size) {
    const float* x       = (const float*)d_in[0];
    const int*   lengths = (const int*)d_in[1];
    // locate W_in robustly (out_lengths scalar may or may not occupy index 2)
    int wi = -1;
    for (int i = 2; i < n_in; ++i)
        if (in_sizes[i] == (HH + II) * HH) { wi = i; break; }
    if (wi < 0) wi = 3;
    const float* Win  = (const float*)d_in[wi + 0];
    const float* b_in = (const float*)d_in[wi + 1];
    const float* Wps  = (const float*)d_in[wi + 2];
    const float* b_ps = (const float*)d_in[wi + 3];
    const float* Wtu  = (const float*)d_in[wi + 4];
    const float* b_tu = (const float*)d_in[wi + 5];
    const float* Wme  = (const float*)d_in[wi + 6];
    const float* b_me = (const float*)d_in[wi + 7];
    const float* Wot  = (const float*)d_in[wi + 8];
    const float* b_ot = (const float*)d_in[wi + 9];
    float* out = (float*)d_out;

    // pre-kernel: W_comb = W_in @ W_pass (tiled) with b_comb folded in
    build_wcomb<<<dim3((HH + II) / 32, HH / 64), 256>>>(Win, Wps, b_in, b_ps);

    size_t smem = sizeof(Smem);
    cudaFuncSetAttribute(delay_rnn_kernel,
                         cudaFuncAttributeMaxDynamicSharedMemorySize, (int)smem);
    delay_rnn_kernel<<<NBLK, NTHR, smem>>>(x, lengths, Win, b_in,
                                           Wtu, b_tu, Wme, b_me, Wot, b_ot, out);
}